// round 11
// baseline (speedup 1.0000x reference)
#include <cuda_runtime.h>
#include <cuda_bf16.h>
#include <stdint.h>

#define N_NODES 100000
#define MAX_E   3200000
#define F_IN    512
#define HID     16
#define N_CLS   64
#define PAD     128           // padded bucket width (Poisson(32) max deg ~70)

// ---------------- scratch (static device globals) ---------------------------
__device__ int   g_pos [N_NODES];                // per-node fill cursor == in-degree
__device__ int   g_srcs[(size_t)N_NODES * PAD];  // padded CSR buckets (51.2 MB)
__device__ int   g_is64;

__device__ __align__(16) float g_hs1[N_NODES * HID];   // x@W1, then dinv-scaled in place
__device__ __align__(16) float g_hs2[N_NODES * HID];   // dinv * relu(prop1 + b1)
__device__ __align__(16) float g_a2 [N_NODES * HID];   // prop2 (pre-W2)

union F2U { float2 f; unsigned long long u; };

// ---------------- init + dtype probe ----------------------------------------
__global__ void k_init(const int* __restrict__ ei32, int nwords, int n) {
    int i = blockIdx.x * blockDim.x + threadIdx.x;
    if (i < n) g_pos[i] = 0;
    if (i == 0 && blockIdx.x == 0) {
        int odd_nonzero = 0;
        #pragma unroll
        for (int k = 0; k < 32; k++) {
            int w = 2 * k + 1;
            if (w < nwords && ei32[w] != 0) odd_nonzero++;
        }
        g_is64 = (odd_nonzero == 0) ? 1 : 0;
    }
}

// ---------------- fused: fill (blocks < nFill) || gemm1 (blocks >= nFill) -----
// fill: bucket CSR build, 4 edges/thread.
// gemm1: h1 = x @ W1 (UNscaled; k_scale applies dinv afterwards).
__global__ __launch_bounds__(256) void k_fill_gemm1(const void* __restrict__ ei,
                                                    int E,
                                                    const float* __restrict__ x,
                                                    const float* __restrict__ W1,
                                                    int n, int nFill) {
    __shared__ __align__(16) ulonglong2 sW[F_IN * 4];   // 32 KB (gemm1 path only)

    if ((int)blockIdx.x < nFill) {
        // ----------------- fill path -----------------
        int t = blockIdx.x * 256 + threadIdx.x;
        int e0 = t * 4;
        if (e0 >= E) return;
        int is64 = g_is64;

        int s[4], d[4], m = 0;
        if (!is64) {
            const int* p = (const int*)ei;
            if (e0 + 4 <= E && (E & 3) == 0) {
                int4 sv = *(const int4*)(p + e0);
                int4 dv = *(const int4*)(p + (size_t)E + e0);
                s[0] = sv.x; s[1] = sv.y; s[2] = sv.z; s[3] = sv.w;
                d[0] = dv.x; d[1] = dv.y; d[2] = dv.z; d[3] = dv.w;
                m = 4;
            } else {
                for (int i = 0; i < 4 && e0 + i < E; i++) {
                    s[m] = p[e0 + i]; d[m] = p[(size_t)E + e0 + i]; m++;
                }
            }
        } else {
            const long long* p = (const long long*)ei;
            for (int i = 0; i < 4 && e0 + i < E; i++) {
                s[m] = (int)p[e0 + i]; d[m] = (int)p[(size_t)E + e0 + i]; m++;
            }
        }

        #pragma unroll
        for (int i = 0; i < 4; i++) {
            if (i < m && (unsigned)s[i] < (unsigned)n && (unsigned)d[i] < (unsigned)n) {
                int slot = atomicAdd(&g_pos[d[i]], 1);
                if (slot < PAD) g_srcs[(size_t)d[i] * PAD + slot] = s[i];
            }
        }
        return;
    }

    // ----------------- gemm1 path -----------------
    for (int i = threadIdx.x; i < F_IN * 4; i += 256) {
        float4 w = ((const float4*)W1)[i];
        F2U a, b;
        a.f = make_float2(w.x, w.y);
        b.f = make_float2(w.z, w.w);
        ulonglong2 u; u.x = a.u; u.y = b.u;
        sW[i] = u;
    }
    __syncthreads();

    int row = (blockIdx.x - nFill) * 256 + threadIdx.x;
    if (row >= n) return;

    const float4* xr = (const float4*)(x + (size_t)row * F_IN);
    unsigned long long acc[8];
    #pragma unroll
    for (int p = 0; p < 8; p++) acc[p] = 0ull;

    #pragma unroll 2
    for (int k4 = 0; k4 < F_IN / 4; k4++) {
        float4 v = xr[k4];
        #pragma unroll
        for (int c = 0; c < 4; c++) {
            float xv = (c == 0) ? v.x : (c == 1) ? v.y : (c == 2) ? v.z : v.w;
            unsigned int xu = __float_as_uint(xv);
            unsigned long long xx;
            asm("mov.b64 %0, {%1, %1};" : "=l"(xx) : "r"(xu));
            const ulonglong2* wp = sW + (size_t)(k4 * 4 + c) * 4;
            #pragma unroll
            for (int h = 0; h < 4; h++) {
                ulonglong2 w = wp[h];               // LDS.128 broadcast
                asm("fma.rn.f32x2 %0, %1, %2, %0;"
                    : "+l"(acc[2 * h])     : "l"(xx), "l"(w.x));
                asm("fma.rn.f32x2 %0, %1, %2, %0;"
                    : "+l"(acc[2 * h + 1]) : "l"(xx), "l"(w.y));
            }
        }
    }

    float4* outp = (float4*)(g_hs1 + (size_t)row * HID);
    #pragma unroll
    for (int q = 0; q < 4; q++) {
        F2U lo, hi; lo.u = acc[2 * q]; hi.u = acc[2 * q + 1];
        outp[q] = make_float4(lo.f.x, lo.f.y, hi.f.x, hi.f.y);
    }
}

// ---------------- scale: hs1 *= dinv[row] (in place) --------------------------
__global__ __launch_bounds__(256) void k_scale(int n) {
    int idx = blockIdx.x * 256 + threadIdx.x;
    if (idx >= n * 4) return;
    int row = idx >> 2;
    float dn = rsqrtf((float)(g_pos[row] + 1));
    float4 v = ((float4*)g_hs1)[idx];
    v.x *= dn; v.y *= dn; v.z *= dn; v.w *= dn;
    ((float4*)g_hs1)[idx] = v;
}

// ---------------- aggregation (packed f32x2, 2 chains + idx prefetch) ---------
__global__ __launch_bounds__(256) void k_aggregate(const float* __restrict__ bias,
                                                   int stage, int n) {
    const ulonglong2* hin;
    float4*           hout;
    if (stage == 1) { hin = (const ulonglong2*)g_hs1; hout = (float4*)g_hs2; }
    else            { hin = (const ulonglong2*)g_hs2; hout = (float4*)g_a2;  }

    int lane = threadIdx.x & 31;
    int node = blockIdx.x * 8 + (threadIdx.x >> 5);
    if (node >= n) return;

    int f4 = lane & 3;
    int nb = lane >> 2;
    int base = node * PAD;              // fits 32-bit (100000*128)
    int cTrue = g_pos[node];
    int c = cTrue < PAD ? cTrue : PAD;

    unsigned long long a01 = 0ull, a23 = 0ull;
    unsigned long long b01 = 0ull, b23 = 0ull;

    int j = nb;
    int s0n = 0, s1n = 0;
    if (j < c)     s0n = g_srcs[base + j];
    if (j + 8 < c) s1n = g_srcs[base + j + 8];

    for (; j < c; j += 16) {
        int s0 = s0n, s1 = s1n;
        int have1 = (j + 8 < c);
        if (j + 16 < c) s0n = g_srcs[base + j + 16];
        if (j + 24 < c) s1n = g_srcs[base + j + 24];

        ulonglong2 v0 = hin[s0 * 4 + f4];
        asm("add.rn.f32x2 %0, %0, %1;" : "+l"(a01) : "l"(v0.x));
        asm("add.rn.f32x2 %0, %0, %1;" : "+l"(a23) : "l"(v0.y));
        if (have1) {
            ulonglong2 v1 = hin[s1 * 4 + f4];
            asm("add.rn.f32x2 %0, %0, %1;" : "+l"(b01) : "l"(v1.x));
            asm("add.rn.f32x2 %0, %0, %1;" : "+l"(b23) : "l"(v1.y));
        }
    }
    asm("add.rn.f32x2 %0, %0, %1;" : "+l"(a01) : "l"(b01));
    asm("add.rn.f32x2 %0, %0, %1;" : "+l"(a23) : "l"(b23));

    #pragma unroll
    for (int off = 16; off >= 4; off >>= 1) {
        unsigned long long t01 = __shfl_down_sync(0xffffffffu, a01, off);
        unsigned long long t23 = __shfl_down_sync(0xffffffffu, a23, off);
        asm("add.rn.f32x2 %0, %0, %1;" : "+l"(a01) : "l"(t01));
        asm("add.rn.f32x2 %0, %0, %1;" : "+l"(a23) : "l"(t23));
    }

    if (nb == 0) {
        ulonglong2 self = hin[node * 4 + f4];
        asm("add.rn.f32x2 %0, %0, %1;" : "+l"(a01) : "l"(self.x));
        asm("add.rn.f32x2 %0, %0, %1;" : "+l"(a23) : "l"(self.y));
        float dn = rsqrtf((float)(cTrue + 1));
        F2U lo, hi; lo.u = a01; hi.u = a23;
        float4 r = make_float4(dn * lo.f.x, dn * lo.f.y, dn * hi.f.x, dn * hi.f.y);
        if (stage == 1) {
            float4 b = ((const float4*)bias)[f4];
            r.x = dn * fmaxf(r.x + b.x, 0.f);
            r.y = dn * fmaxf(r.y + b.y, 0.f);
            r.z = dn * fmaxf(r.z + b.z, 0.f);
            r.w = dn * fmaxf(r.w + b.w, 0.f);
        }
        hout[node * 4 + f4] = r;
    }
}

// ---------------- GEMM2: out = a2 @ W2 + b2 (100000x16 @ 16x64) ---------------
__global__ __launch_bounds__(256) void k_gemm2(const float* __restrict__ W2,
                                               const float* __restrict__ b2,
                                               float* __restrict__ out,
                                               int n) {
    __shared__ __align__(16) float4 sW[HID * (N_CLS / 4)];
    __shared__ __align__(16) float4 sb[N_CLS / 4];
    {
        int t = threadIdx.x;
        sW[t] = ((const float4*)W2)[t];
        if (t < N_CLS / 4) sb[t] = ((const float4*)b2)[t];
    }
    __syncthreads();

    int idx = blockIdx.x * 256 + threadIdx.x;
    if (idx >= n * (N_CLS / 4)) return;
    int row = idx >> 4;
    int j4 = idx & 15;

    const float* a = g_a2 + (size_t)row * HID;
    float4 acc = sb[j4];
    #pragma unroll
    for (int k = 0; k < HID; k++) {
        float av = a[k];
        float4 w = sW[k * (N_CLS / 4) + j4];
        acc.x = fmaf(av, w.x, acc.x);
        acc.y = fmaf(av, w.y, acc.y);
        acc.z = fmaf(av, w.z, acc.z);
        acc.w = fmaf(av, w.w, acc.w);
    }
    ((float4*)out)[idx] = acc;
}

// ---------------- launch --------------------------------------------------------
extern "C" void kernel_launch(void* const* d_in, const int* in_sizes, int n_in,
                              void* d_out, int out_size) {
    const float* x  = (const float*)d_in[0];
    const void*  ei = d_in[1];
    const float* W1 = (const float*)d_in[2];
    const float* b1 = (const float*)d_in[3];
    const float* W2 = (const float*)d_in[4];
    const float* b2 = (const float*)d_in[5];
    float*       out = (float*)d_out;

    int E = in_sizes[1] / 2;
    if (E > MAX_E) E = MAX_E;
    int n = out_size / N_CLS;
    if (n > N_NODES) n = N_NODES;

    int gN   = (n + 255) / 256;
    int gF   = ((E + 3) / 4 + 255) / 256;
    int gSc  = (n * 4 + 255) / 256;
    int gAgg = (n + 7) / 8;
    int gG2  = (n * (N_CLS / 4) + 255) / 256;

    k_init      <<<gN, 256>>>((const int*)ei, in_sizes[1], n);
    k_fill_gemm1<<<gF + gN, 256>>>(ei, E, x, W1, n, gF);
    k_scale     <<<gSc, 256>>>(n);
    k_aggregate <<<gAgg, 256>>>(b1, 1, n);
    k_aggregate <<<gAgg, 256>>>(b2, 2, n);
    k_gemm2     <<<gG2, 256>>>(W2, b2, out, n);
}

// round 12
// speedup vs baseline: 1.2936x; 1.2936x over previous
#include <cuda_runtime.h>
#include <cuda_bf16.h>
#include <stdint.h>

#define N_NODES 100000
#define MAX_E   3200000
#define F_IN    512
#define HID     16
#define N_CLS   64
#define PAD     128           // padded bucket width (Poisson(32) max deg ~70)

// ---------------- scratch (static device globals) ---------------------------
__device__ int   g_pos [N_NODES];                // per-node fill cursor == in-degree
__device__ int   g_srcs[(size_t)N_NODES * PAD];  // padded CSR buckets (51.2 MB)
__device__ int   g_is64;

__device__ __align__(16) float g_hs1[N_NODES * HID];   // dinv * (x @ W1)
__device__ __align__(16) float g_hs2[N_NODES * HID];   // dinv * relu(prop1 + b1)

union F2U { float2 f; unsigned long long u; };

// ---------------- init + dtype probe ----------------------------------------
__global__ void k_init(const int* __restrict__ ei32, int nwords, int n) {
    int i = blockIdx.x * blockDim.x + threadIdx.x;
    if (i < n) g_pos[i] = 0;
    if (i == 0 && blockIdx.x == 0) {
        int odd_nonzero = 0;
        #pragma unroll
        for (int k = 0; k < 32; k++) {
            int w = 2 * k + 1;
            if (w < nwords && ei32[w] != 0) odd_nonzero++;
        }
        g_is64 = (odd_nonzero == 0) ? 1 : 0;
    }
}

// ---------------- bucket fill (4 edges / thread) ------------------------------
__global__ __launch_bounds__(256) void k_fill(const void* __restrict__ ei,
                                              int E, int n) {
    int t = blockIdx.x * blockDim.x + threadIdx.x;
    int e0 = t * 4;
    if (e0 >= E) return;
    int is64 = g_is64;

    int s[4], d[4], m = 0;
    if (!is64) {
        const int* p = (const int*)ei;
        if (e0 + 4 <= E && (E & 3) == 0) {
            int4 sv = *(const int4*)(p + e0);
            int4 dv = *(const int4*)(p + (size_t)E + e0);
            s[0] = sv.x; s[1] = sv.y; s[2] = sv.z; s[3] = sv.w;
            d[0] = dv.x; d[1] = dv.y; d[2] = dv.z; d[3] = dv.w;
            m = 4;
        } else {
            for (int i = 0; i < 4 && e0 + i < E; i++) {
                s[m] = p[e0 + i]; d[m] = p[(size_t)E + e0 + i]; m++;
            }
        }
    } else {
        const long long* p = (const long long*)ei;
        for (int i = 0; i < 4 && e0 + i < E; i++) {
            s[m] = (int)p[e0 + i]; d[m] = (int)p[(size_t)E + e0 + i]; m++;
        }
    }

    #pragma unroll
    for (int i = 0; i < 4; i++) {
        if (i < m && (unsigned)s[i] < (unsigned)n && (unsigned)d[i] < (unsigned)n) {
            int slot = atomicAdd(&g_pos[d[i]], 1);
            if (slot < PAD) g_srcs[(size_t)d[i] * PAD + slot] = s[i];
        }
    }
}

// ---------------- GEMM1: hs1 = dinv ⊙ (x @ W1), f32x2 FMA ---------------------
__global__ __launch_bounds__(256) void k_gemm1(const float* __restrict__ x,
                                               const float* __restrict__ W1,
                                               int n) {
    __shared__ __align__(16) ulonglong2 sW[F_IN * 4];   // 32 KB
    for (int i = threadIdx.x; i < F_IN * 4; i += 256) {
        float4 w = ((const float4*)W1)[i];
        F2U a, b;
        a.f = make_float2(w.x, w.y);
        b.f = make_float2(w.z, w.w);
        ulonglong2 u; u.x = a.u; u.y = b.u;
        sW[i] = u;
    }
    __syncthreads();

    int row = blockIdx.x * 256 + threadIdx.x;
    if (row >= n) return;

    const float4* xr = (const float4*)(x + (size_t)row * F_IN);
    unsigned long long acc[8];
    #pragma unroll
    for (int p = 0; p < 8; p++) acc[p] = 0ull;

    #pragma unroll 2
    for (int k4 = 0; k4 < F_IN / 4; k4++) {
        float4 v = xr[k4];
        #pragma unroll
        for (int c = 0; c < 4; c++) {
            float xv = (c == 0) ? v.x : (c == 1) ? v.y : (c == 2) ? v.z : v.w;
            unsigned int xu = __float_as_uint(xv);
            unsigned long long xx;
            asm("mov.b64 %0, {%1, %1};" : "=l"(xx) : "r"(xu));
            const ulonglong2* wp = sW + (size_t)(k4 * 4 + c) * 4;
            #pragma unroll
            for (int h = 0; h < 4; h++) {
                ulonglong2 w = wp[h];               // LDS.128 broadcast
                asm("fma.rn.f32x2 %0, %1, %2, %0;"
                    : "+l"(acc[2 * h])     : "l"(xx), "l"(w.x));
                asm("fma.rn.f32x2 %0, %1, %2, %0;"
                    : "+l"(acc[2 * h + 1]) : "l"(xx), "l"(w.y));
            }
        }
    }

    float dn = rsqrtf((float)(g_pos[row] + 1));
    float4* outp = (float4*)(g_hs1 + (size_t)row * HID);
    #pragma unroll
    for (int q = 0; q < 4; q++) {
        F2U lo, hi; lo.u = acc[2 * q]; hi.u = acc[2 * q + 1];
        outp[q] = make_float4(dn * lo.f.x, dn * lo.f.y, dn * hi.f.x, dn * hi.f.y);
    }
}

// ---------------- stage-1 aggregation (identical to round-10 best) ------------
// hs2 = dinv * relu(dinv*(sum hs1[s] + hs1[node]) + b1)
__global__ __launch_bounds__(256) void k_aggregate(const float* __restrict__ bias,
                                                   int n) {
    const ulonglong2* hin  = (const ulonglong2*)g_hs1;
    float4*           hout = (float4*)g_hs2;

    int lane = threadIdx.x & 31;
    int node = blockIdx.x * 8 + (threadIdx.x >> 5);
    if (node >= n) return;

    int f4 = lane & 3;
    int nb = lane >> 2;
    int base = node * PAD;
    int cTrue = g_pos[node];
    int c = cTrue < PAD ? cTrue : PAD;

    unsigned long long a01 = 0ull, a23 = 0ull;
    unsigned long long b01 = 0ull, b23 = 0ull;

    int j = nb;
    int s0n = 0, s1n = 0;
    if (j < c)     s0n = g_srcs[base + j];
    if (j + 8 < c) s1n = g_srcs[base + j + 8];

    for (; j < c; j += 16) {
        int s0 = s0n, s1 = s1n;
        int have1 = (j + 8 < c);
        if (j + 16 < c) s0n = g_srcs[base + j + 16];
        if (j + 24 < c) s1n = g_srcs[base + j + 24];

        ulonglong2 v0 = hin[s0 * 4 + f4];
        asm("add.rn.f32x2 %0, %0, %1;" : "+l"(a01) : "l"(v0.x));
        asm("add.rn.f32x2 %0, %0, %1;" : "+l"(a23) : "l"(v0.y));
        if (have1) {
            ulonglong2 v1 = hin[s1 * 4 + f4];
            asm("add.rn.f32x2 %0, %0, %1;" : "+l"(b01) : "l"(v1.x));
            asm("add.rn.f32x2 %0, %0, %1;" : "+l"(b23) : "l"(v1.y));
        }
    }
    asm("add.rn.f32x2 %0, %0, %1;" : "+l"(a01) : "l"(b01));
    asm("add.rn.f32x2 %0, %0, %1;" : "+l"(a23) : "l"(b23));

    #pragma unroll
    for (int off = 16; off >= 4; off >>= 1) {
        unsigned long long t01 = __shfl_down_sync(0xffffffffu, a01, off);
        unsigned long long t23 = __shfl_down_sync(0xffffffffu, a23, off);
        asm("add.rn.f32x2 %0, %0, %1;" : "+l"(a01) : "l"(t01));
        asm("add.rn.f32x2 %0, %0, %1;" : "+l"(a23) : "l"(t23));
    }

    if (nb == 0) {
        ulonglong2 self = hin[node * 4 + f4];
        asm("add.rn.f32x2 %0, %0, %1;" : "+l"(a01) : "l"(self.x));
        asm("add.rn.f32x2 %0, %0, %1;" : "+l"(a23) : "l"(self.y));
        float dn = rsqrtf((float)(cTrue + 1));
        F2U lo, hi; lo.u = a01; hi.u = a23;
        float4 b = ((const float4*)bias)[f4];
        float4 r;
        r.x = dn * fmaxf(dn * lo.f.x + b.x, 0.f);
        r.y = dn * fmaxf(dn * lo.f.y + b.y, 0.f);
        r.z = dn * fmaxf(dn * hi.f.x + b.z, 0.f);
        r.w = dn * fmaxf(dn * hi.f.y + b.w, 0.f);
        hout[node * 4 + f4] = r;
    }
}

// ---------------- stage-2 aggregation fused with GEMM2 ------------------------
// a2 = dinv*(sum hs2[s] + hs2[node]) computed in registers (lanes 0-3 hold it),
// then out[node] = a2 @ W2 + b2: each lane produces 2 output columns.
__global__ __launch_bounds__(256) void k_agg2(const float* __restrict__ W2,
                                              const float* __restrict__ b2,
                                              float* __restrict__ out, int n) {
    __shared__ __align__(16) float2 sW2[HID * (N_CLS / 2)];   // 4 KB [k][colpair]
    ((float4*)sW2)[threadIdx.x] = ((const float4*)W2)[threadIdx.x];  // 256 float4
    __syncthreads();

    const ulonglong2* hin = (const ulonglong2*)g_hs2;

    int lane = threadIdx.x & 31;
    int node = blockIdx.x * 8 + (threadIdx.x >> 5);
    if (node >= n) return;

    int f4 = lane & 3;
    int nb = lane >> 2;
    int base = node * PAD;
    int cTrue = g_pos[node];
    int c = cTrue < PAD ? cTrue : PAD;

    unsigned long long a01 = 0ull, a23 = 0ull;
    unsigned long long b01 = 0ull, b23 = 0ull;

    int j = nb;
    int s0n = 0, s1n = 0;
    if (j < c)     s0n = g_srcs[base + j];
    if (j + 8 < c) s1n = g_srcs[base + j + 8];

    for (; j < c; j += 16) {
        int s0 = s0n, s1 = s1n;
        int have1 = (j + 8 < c);
        if (j + 16 < c) s0n = g_srcs[base + j + 16];
        if (j + 24 < c) s1n = g_srcs[base + j + 24];

        ulonglong2 v0 = hin[s0 * 4 + f4];
        asm("add.rn.f32x2 %0, %0, %1;" : "+l"(a01) : "l"(v0.x));
        asm("add.rn.f32x2 %0, %0, %1;" : "+l"(a23) : "l"(v0.y));
        if (have1) {
            ulonglong2 v1 = hin[s1 * 4 + f4];
            asm("add.rn.f32x2 %0, %0, %1;" : "+l"(b01) : "l"(v1.x));
            asm("add.rn.f32x2 %0, %0, %1;" : "+l"(b23) : "l"(v1.y));
        }
    }
    asm("add.rn.f32x2 %0, %0, %1;" : "+l"(a01) : "l"(b01));
    asm("add.rn.f32x2 %0, %0, %1;" : "+l"(a23) : "l"(b23));

    #pragma unroll
    for (int off = 16; off >= 4; off >>= 1) {
        unsigned long long t01 = __shfl_down_sync(0xffffffffu, a01, off);
        unsigned long long t23 = __shfl_down_sync(0xffffffffu, a23, off);
        asm("add.rn.f32x2 %0, %0, %1;" : "+l"(a01) : "l"(t01));
        asm("add.rn.f32x2 %0, %0, %1;" : "+l"(a23) : "l"(t23));
    }

    // self + scale on all lanes (only lanes 0-3 carry valid totals; shfl below
    // reads srcLane 0-3 only)
    ulonglong2 self = hin[node * 4 + f4];
    asm("add.rn.f32x2 %0, %0, %1;" : "+l"(a01) : "l"(self.x));
    asm("add.rn.f32x2 %0, %0, %1;" : "+l"(a23) : "l"(self.y));
    float dn = rsqrtf((float)(cTrue + 1));
    F2U lo, hi; lo.u = a01; hi.u = a23;
    float r0 = dn * lo.f.x, r1 = dn * lo.f.y, r2 = dn * hi.f.x, r3 = dn * hi.f.y;

    // fused GEMM2: lane computes output columns (2*lane, 2*lane+1)
    F2U acc; acc.f = ((const float2*)b2)[lane];
    #pragma unroll
    for (int k = 0; k < HID; k++) {
        int srcLane = k >> 2;
        float av;
        if ((k & 3) == 0)      av = __shfl_sync(0xffffffffu, r0, srcLane);
        else if ((k & 3) == 1) av = __shfl_sync(0xffffffffu, r1, srcLane);
        else if ((k & 3) == 2) av = __shfl_sync(0xffffffffu, r2, srcLane);
        else                   av = __shfl_sync(0xffffffffu, r3, srcLane);
        unsigned int au = __float_as_uint(av);
        unsigned long long ax;
        asm("mov.b64 %0, {%1, %1};" : "=l"(ax) : "r"(au));
        F2U w; w.f = sW2[k * (N_CLS / 2) + lane];   // LDS.64, conflict-free
        asm("fma.rn.f32x2 %0, %1, %2, %0;" : "+l"(acc.u) : "l"(ax), "l"(w.u));
    }
    ((float2*)out)[node * (N_CLS / 2) + lane] = acc.f;
}

// ---------------- launch --------------------------------------------------------
extern "C" void kernel_launch(void* const* d_in, const int* in_sizes, int n_in,
                              void* d_out, int out_size) {
    const float* x  = (const float*)d_in[0];
    const void*  ei = d_in[1];
    const float* W1 = (const float*)d_in[2];
    const float* b1 = (const float*)d_in[3];
    const float* W2 = (const float*)d_in[4];
    const float* b2 = (const float*)d_in[5];
    float*       out = (float*)d_out;

    int E = in_sizes[1] / 2;
    if (E > MAX_E) E = MAX_E;
    int n = out_size / N_CLS;
    if (n > N_NODES) n = N_NODES;

    int gN   = (n + 255) / 256;
    int gE4  = ((E + 3) / 4 + 255) / 256;
    int gAgg = (n + 7) / 8;

    k_init     <<<gN, 256>>>((const int*)ei, in_sizes[1], n);
    k_fill     <<<gE4, 256>>>(ei, E, n);
    k_gemm1    <<<gN, 256>>>(x, W1, n);
    k_aggregate<<<gAgg, 256>>>(b1, n);
    k_agg2     <<<gAgg, 256>>>(W2, b2, out, n);
}